// round 17
// baseline (speedup 1.0000x reference)
#include <cuda_runtime.h>
#include <cuda_bf16.h>
#include <mma.h>
#include <math.h>

using namespace nvcuda;

#define TT 512
#define BB 32
#define DD 768
#define HH 256
#define GG 1024   // 4*H
#define KK 32
#define NKC 48    // 768/16 k-chunks

typedef unsigned long long ull;

// ---------------- packed f32x2 helpers ----------------
__device__ __forceinline__ ull pack2(float x, float y) {
    ull r; asm("mov.b64 %0,{%1,%2};" : "=l"(r) : "f"(x), "f"(y)); return r;
}
__device__ __forceinline__ void unpack2(ull v, float& x, float& y) {
    asm("mov.b64 {%0,%1},%2;" : "=f"(x), "=f"(y) : "l"(v));
}
__device__ __forceinline__ ull ffma2(ull a, ull b, ull c) {
    ull d; asm("fma.rn.f32x2 %0,%1,%2,%3;" : "=l"(d) : "l"(a), "l"(b), "l"(c)); return d;
}

// ---------------- device scratch ----------------
__device__ float d_pre[(size_t)2 * TT * BB * GG];      // [dir][m][4H]  (m = t*32+b)
__device__ float d_hall[(size_t)2 * TT * BB * HH];
__device__ float d_em[(size_t)BB * TT * KK];
__device__ unsigned char d_hist[(size_t)BB * 511 * KK];
__device__ float d_nll[BB];
__device__ int d_last[BB];
// 2-way split bf16 operands
__device__ __nv_bfloat16 d_ax[(size_t)2 * 2 * NKC * 16384 * 16];
__device__ __nv_bfloat16 d_bw[(size_t)2 * 2 * NKC * 1024 * 16];

__device__ __forceinline__ float sigmoidf_(float v) { return 1.f / (1.f + __expf(-v)); }
__device__ __forceinline__ unsigned smem_u32(const void* p) {
    unsigned a;
    asm("{ .reg .u64 t; cvta.to.shared.u64 t, %1; cvt.u32.u64 %0, t; }" : "=r"(a) : "l"(p));
    return a;
}

// dummy launch for ncu capture alignment (k_lstm stays launch #4)
__global__ void k_dummy() {}

// ============ K0b: split x and W into 2-component bf16 planes =============
__global__ void __launch_bounds__(256) k_split(
    const float* __restrict__ x, const int* __restrict__ lengths,
    const float* __restrict__ Wf, const float* __restrict__ Wb)
{
    const unsigned u = blockIdx.x * 256 + threadIdx.x;
    const unsigned NA = 2u * NKC * 16384;
    const float* src;
    size_t plane_row;
    bool isA;
    unsigned dir, kc;
    if (u < NA) {
        isA = true;
        unsigned m = u & 16383u;
        unsigned q = u >> 14;
        kc = q % NKC; dir = q / NKC;
        int t = m >> 5, b = m & 31;
        int st = t;
        if (dir) { int L = __ldg(&lengths[b]); st = (t < L) ? (L - 1 - t) : t; }
        src = x + ((size_t)b * TT + st) * DD + kc * 16;
        plane_row = m;
    } else {
        isA = false;
        unsigned v = u - NA;
        unsigned n = v & 1023u;
        unsigned q = v >> 10;
        kc = q % NKC; dir = q / NKC;
        const float* W = dir ? Wb : Wf;
        src = W + (size_t)n * DD + kc * 16;
        plane_row = n;
    }
    unsigned hw[8], mw[8];
#pragma unroll
    for (int i = 0; i < 8; i++) {
        unsigned short hh[2], mm2[2];
#pragma unroll
        for (int p = 0; p < 2; p++) {
            float xv = __ldg(&src[i * 2 + p]);
            __nv_bfloat16 bh = __float2bfloat16_rn(xv);
            float r1 = xv - __bfloat162float(bh);
            __nv_bfloat16 bm = __float2bfloat16_rn(r1);
            hh[p] = __bfloat16_as_ushort(bh);
            mm2[p] = __bfloat16_as_ushort(bm);
        }
        hw[i] = (unsigned)hh[0] | ((unsigned)hh[1] << 16);
        mw[i] = (unsigned)mm2[0] | ((unsigned)mm2[1] << 16);
    }
    if (isA) {
#pragma unroll
        for (int s = 0; s < 2; s++) {
            size_t plane = (size_t)(dir * 2 + s) * NKC + kc;
            uint4* dst = reinterpret_cast<uint4*>(d_ax + (plane * 16384 + plane_row) * 16);
            const unsigned* w = (s == 0) ? hw : mw;
            dst[0] = make_uint4(w[0], w[1], w[2], w[3]);
            dst[1] = make_uint4(w[4], w[5], w[6], w[7]);
        }
    } else {
#pragma unroll
        for (int s = 0; s < 2; s++) {
            size_t plane = (size_t)(dir * 2 + s) * NKC + kc;
            uint4* dst = reinterpret_cast<uint4*>(d_bw + (plane * 1024 + plane_row) * 16);
            const unsigned* w = (s == 0) ? hw : mw;
            dst[0] = make_uint4(w[0], w[1], w[2], w[3]);
            dst[1] = make_uint4(w[4], w[5], w[6], w[7]);
        }
    }
}

// ============ K1: standalone wmma GEMM, 64x64 tiles (proven R14) ==========
__global__ void __launch_bounds__(256, 2) k_gemm()
{
    __shared__ __nv_bfloat16 sA[2][2][64 * 24];
    __shared__ __nv_bfloat16 sB[2][2][64 * 24];

    const int m0  = blockIdx.x * 64;
    const int n0  = blockIdx.y * 64;
    const int dir = blockIdx.z;
    const int tid = threadIdx.x;
    const int wid = tid >> 5;
    const int warp_m = (wid & 3) * 16;
    const int warp_n = (wid >> 2) * 32;

    const bool isB = tid >= 128;
    const int lt = tid & 127;
    const int row = lt >> 1, half = lt & 1;

    wmma::fragment<wmma::accumulator, 16, 16, 16, float> ac[2];
    wmma::fill_fragment(ac[0], 0.0f);
    wmma::fill_fragment(ac[1], 0.0f);

    uint4 r[2];
    auto load_regs = [&](int kc) {
#pragma unroll
        for (int s = 0; s < 2; s++) {
            size_t plane = (size_t)(dir * 2 + s) * NKC + kc;
            if (!isB)
                r[s] = reinterpret_cast<const uint4*>(d_ax)[(plane * 16384 + m0 + row) * 2 + half];
            else
                r[s] = reinterpret_cast<const uint4*>(d_bw)[(plane * 1024 + n0 + row) * 2 + half];
        }
    };
    auto store_regs = [&](int cb) {
        const int ui = row * 3 + half;
#pragma unroll
        for (int s = 0; s < 2; s++) {
            if (!isB) reinterpret_cast<uint4*>(sA[cb][s])[ui] = r[s];
            else      reinterpret_cast<uint4*>(sB[cb][s])[ui] = r[s];
        }
    };

    load_regs(0);
    store_regs(0);
    __syncthreads();

    for (int c = 0; c < NKC; c++) {
        const int cb = c & 1;
        if (c + 1 < NKC) load_regs(c + 1);

        const int pa_t[3] = {0, 0, 1};
        const int pb_t[3] = {0, 1, 0};
#pragma unroll
        for (int p = 0; p < 3; p++) {
            wmma::fragment<wmma::matrix_a, 16, 16, 16, __nv_bfloat16, wmma::row_major> af;
            wmma::fragment<wmma::matrix_b, 16, 16, 16, __nv_bfloat16, wmma::col_major> bfr;
            wmma::load_matrix_sync(af, sA[cb][pa_t[p]] + warp_m * 24, 24);
            wmma::load_matrix_sync(bfr, sB[cb][pb_t[p]] + warp_n * 24, 24);
            wmma::mma_sync(ac[0], af, bfr, ac[0]);
            wmma::load_matrix_sync(bfr, sB[cb][pb_t[p]] + (warp_n + 16) * 24, 24);
            wmma::mma_sync(ac[1], af, bfr, ac[1]);
        }
        __syncthreads();
        if (c + 1 < NKC) {
            store_regs((c + 1) & 1);
            __syncthreads();
        }
    }

    float* dst = d_pre + ((size_t)dir * 16384 + m0 + warp_m) * GG + n0 + warp_n;
    wmma::store_matrix_sync(dst, ac[0], GG, wmma::mem_row_major);
    wmma::store_matrix_sync(dst + 16, ac[1], GG, wmma::mem_row_major);
}

// ============ K2: LSTM recurrence — 8-CTA cluster, DSMEM h push ===========
// grid 128, cluster 8. group g = bid>>3 (dir = g>>3, bg = g&7), jc = ctarank.
// CTA owns j-slice jc*32..+32 for 4 batches; h exchanged via st.shared::cluster,
// one barrier.cluster per step. No global counters.
__global__ void __launch_bounds__(256, 1) __cluster_dims__(8, 1, 1) k_lstm(
    const float* __restrict__ Whf, const float* __restrict__ Whb,
    const float* __restrict__ bf_, const float* __restrict__ bb_)
{
    const int bid = blockIdx.x;
    const int g = bid >> 3;
    const int dir = g >> 3;
    const int bg = g & 7;
    unsigned jc;
    asm("mov.u32 %0, %%cluster_ctarank;" : "=r"(jc));
    const float* __restrict__ Whh = dir ? Whb : Whf;
    const float* __restrict__ bias = dir ? bb_ : bf_;
    const int tid = threadIdx.x;
    const int jj = tid >> 3;
    const int kc = tid & 7;
    const int j = jc * 32 + jj;

    float w[4][32];
#pragma unroll
    for (int gg = 0; gg < 4; gg++)
#pragma unroll
        for (int kk = 0; kk < 32; kk++)
            w[gg][kk] = __ldg(&Whh[(size_t)(gg * HH + j) * HH + (kk * 8 + kc)]);

    const float bv0 = __ldg(&bias[(tid >> 7) * HH + jc * 32 + (tid & 31)]);
    const float bv1 = __ldg(&bias[((tid >> 7) + 2) * HH + jc * 32 + (tid & 31)]);

    __shared__ __align__(16) float h_s[2][HH][4];   // full h for 4 batches (peers push)
    __shared__ float pre_s[2][512];

    // peer h_s base addresses (mapa once)
    unsigned peer[8];
    {
        unsigned hbase = smem_u32(&h_s[0][0][0]);
#pragma unroll
        for (unsigned r = 0; r < 8; r++)
            asm("mapa.shared::cluster.u32 %0, %1, %2;" : "=r"(peer[r]) : "r"(hbase), "r"(r));
    }

    // zero own h_s[0]
#pragma unroll
    for (int q = 0; q < 4; q++) {
        int i = tid + q * 256;
        h_s[0][i & 255][i >> 8] = 0.f;
    }
    float cst[4] = {0.f, 0.f, 0.f, 0.f};

    asm volatile("barrier.cluster.arrive.aligned;" ::: "memory");
    asm volatile("barrier.cluster.wait.aligned;" ::: "memory");

    for (int t = 0; t < TT; t++) {
        const int par = t & 1;
        // load pre (gemm output, complete before this kernel)
        {
            size_t pbase = (((size_t)dir * TT + t) * BB + bg * 4) * GG;
            int i0 = tid, i1 = tid + 256;
            float pv0 = __ldcg(&d_pre[pbase + (size_t)((i0 >> 5) & 3) * GG + (i0 >> 7) * HH + jc * 32 + (i0 & 31)]) + bv0;
            float pv1 = __ldcg(&d_pre[pbase + (size_t)((i1 >> 5) & 3) * GG + (i1 >> 7) * HH + jc * 32 + (i1 & 31)]) + bv1;
            pre_s[par][tid] = pv0;
            pre_s[par][tid + 256] = pv1;
        }
        __syncthreads();

        ull acc[4][2];
#pragma unroll
        for (int gg = 0; gg < 4; gg++) { acc[gg][0] = 0ull; acc[gg][1] = 0ull; }
#pragma unroll
        for (int kk = 0; kk < 32; kk++) {
            int k = kk * 8 + kc;
            ull hp0 = *reinterpret_cast<const ull*>(&h_s[par][k][0]);
            ull hp1 = *reinterpret_cast<const ull*>(&h_s[par][k][2]);
#pragma unroll
            for (int gg = 0; gg < 4; gg++) {
                ull wd = pack2(w[gg][kk], w[gg][kk]);
                acc[gg][0] = ffma2(wd, hp0, acc[gg][0]);
                acc[gg][1] = ffma2(wd, hp1, acc[gg][1]);
            }
        }
        float s[4][4];
#pragma unroll
        for (int gg = 0; gg < 4; gg++) {
            unpack2(acc[gg][0], s[gg][0], s[gg][1]);
            unpack2(acc[gg][1], s[gg][2], s[gg][3]);
        }
#pragma unroll
        for (int d = 1; d < 8; d <<= 1)
#pragma unroll
            for (int gg = 0; gg < 4; gg++)
#pragma unroll
                for (int b = 0; b < 4; b++)
                    s[gg][b] += __shfl_xor_sync(0xffffffffu, s[gg][b], d);

        if (kc == 0) {
#pragma unroll
            for (int b = 0; b < 4; b++) {
                float gi = s[0][b] + pre_s[par][0 * 128 + b * 32 + jj];
                float gf = s[1][b] + pre_s[par][1 * 128 + b * 32 + jj];
                float gg2 = s[2][b] + pre_s[par][2 * 128 + b * 32 + jj];
                float go = s[3][b] + pre_s[par][3 * 128 + b * 32 + jj];
                float c = sigmoidf_(gf) * cst[b] + sigmoidf_(gi) * tanhf(gg2);
                cst[b] = c;
                float h = sigmoidf_(go) * tanhf(c);
                // push h to all 8 cluster CTAs' h_s[par^1][j][b]
                unsigned off = (unsigned)((par ^ 1) * 4096 + j * 16 + b * 4);
#pragma unroll
                for (unsigned r = 0; r < 8; r++)
                    asm volatile("st.shared::cluster.f32 [%0], %1;"
                                 :: "r"(peer[r] + off), "f"(h) : "memory");
                d_hall[(((size_t)dir * TT + t) * BB + bg * 4 + b) * HH + j] = h;
            }
        }
        asm volatile("barrier.cluster.arrive.aligned;" ::: "memory");
        asm volatile("barrier.cluster.wait.aligned;" ::: "memory");
    }
}

// ============ K3: emissions — 256 blocks of 64 timesteps ==================
__global__ void __launch_bounds__(256) k_emis(
    const int* __restrict__ lengths,
    const float* __restrict__ Wclf, const float* __restrict__ bclf)
{
    const int b = blockIdx.x;
    const int tc = blockIdx.y;
    const int tid = threadIdx.x;
    const int k = tid >> 3;
    const int c8 = tid & 7;
    const int L = __ldg(&lengths[b]);

    ull wreg[32];
#pragma unroll
    for (int q = 0; q < 32; q++) {
        int p = q * 8 + c8;
        wreg[q] = pack2(__ldg(&Wclf[(size_t)k * 512 + 2 * p]),
                        __ldg(&Wclf[(size_t)k * 512 + 2 * p + 1]));
    }
    const float bias = __ldg(&bclf[k]);

    __shared__ float hs[2][512];

    auto load_row = [&](int t, float& v0, float& v1) {
        v0 = d_hall[(((size_t)0 * TT + t) * BB + b) * HH + tid];
        int st = (t < L) ? (L - 1 - t) : t;
        v1 = d_hall[(((size_t)1 * TT + st) * BB + b) * HH + tid];
    };

    float v0, v1;
    load_row(tc * 64, v0, v1);
    for (int tt = 0; tt < 64; tt++) {
        const int t = tc * 64 + tt;
        const int par = tt & 1;
        hs[par][tid] = v0;
        hs[par][tid + 256] = v1;
        __syncthreads();
        if (tt + 1 < 64) load_row(t + 1, v0, v1);

        ull acc = 0ull;
#pragma unroll
        for (int q = 0; q < 32; q++) {
            int p = q * 8 + c8;
            acc = ffma2(wreg[q], *reinterpret_cast<const ull*>(&hs[par][2 * p]), acc);
        }
        float lo, hi;
        unpack2(acc, lo, hi);
        float tot = lo + hi;
#pragma unroll
        for (int d = 1; d < 8; d <<= 1)
            tot += __shfl_xor_sync(0xffffffffu, tot, d);
        if (c8 == 0)
            d_em[((size_t)b * TT + t) * KK + k] = tot + bias;
    }
}

// ---------------- warp float max via REDUX ----------------
__device__ __forceinline__ float warp_max32(float x) {
    int k = __float_as_int(x);
    k = (k >= 0) ? k : (k ^ 0x7fffffff);
    int m = __reduce_max_sync(0xffffffffu, k);
    m = (m >= 0) ? m : (m ^ 0x7fffffff);
    return __int_as_float(m);
}

// ============ K4: CRF forward + Viterbi — em staged in 64KB smem ==========
__global__ void __launch_bounds__(64) k_crf(
    const int* __restrict__ lengths, const int* __restrict__ targets,
    const float* __restrict__ st, const float* __restrict__ en,
    const float* __restrict__ trans)
{
    extern __shared__ float em_s[];   // [TT*KK] = 64KB
    const int b = blockIdx.x;
    const int wid = threadIdx.x >> 5;
    const int j = threadIdx.x & 31;
    const int L = __ldg(&lengths[b]);

    // stage em[b] into smem
    {
        const float4* src = reinterpret_cast<const float4*>(d_em + (size_t)b * TT * KK);
        float4* dst = reinterpret_cast<float4*>(em_s);
        for (int i = threadIdx.x; i < (TT * KK) / 4; i += 64) dst[i] = src[i];
    }
    __syncthreads();

    float e0 = em_s[j];

    if (wid == 0) {
        float etr[32];
#pragma unroll
        for (int i = 0; i < 32; i++) etr[i] = __expf(__ldg(&trans[i * 32 + j]));
        float alpha = __ldg(&st[j]) + e0;
        for (int t = 1; t < L; t++) {
            float e_cur = em_s[t * 32 + j];
            float m = warp_max32(alpha);
            float ea = __expf(alpha - m);
            float s0 = 0.f, s1 = 0.f, s2 = 0.f, s3 = 0.f;
#pragma unroll
            for (int i = 0; i < 32; i += 4) {
                s0 = fmaf(__shfl_sync(0xffffffffu, ea, i + 0), etr[i + 0], s0);
                s1 = fmaf(__shfl_sync(0xffffffffu, ea, i + 1), etr[i + 1], s1);
                s2 = fmaf(__shfl_sync(0xffffffffu, ea, i + 2), etr[i + 2], s2);
                s3 = fmaf(__shfl_sync(0xffffffffu, ea, i + 3), etr[i + 3], s3);
            }
            alpha = m + __logf((s0 + s1) + (s2 + s3)) + e_cur;
        }
        float a = alpha + __ldg(&en[j]);
        float m2 = warp_max32(a);
        float ssum2 = __expf(a - m2);
#pragma unroll
        for (int o = 16; o; o >>= 1) ssum2 += __shfl_xor_sync(0xffffffffu, ssum2, o);
        float logZ = m2 + __logf(ssum2);
        float np = 0.f;
        for (int t = 1 + j; t < L; t += 32) {
            int pt = __ldg(&targets[b * TT + t - 1]);
            int ct = __ldg(&targets[b * TT + t]);
            np += __ldg(&trans[pt * 32 + ct]) + em_s[t * 32 + ct];
        }
#pragma unroll
        for (int o = 16; o; o >>= 1) np += __shfl_xor_sync(0xffffffffu, np, o);
        if (j == 0) {
            int tg0 = __ldg(&targets[b * TT + 0]);
            int tgl = __ldg(&targets[b * TT + L - 1]);
            float num = __ldg(&st[tg0]) + em_s[tg0] + np + __ldg(&en[tgl]);
            d_nll[b] = num - logZ;
        }
    } else {
        float trj[32];
#pragma unroll
        for (int i = 0; i < 32; i++) trj[i] = __ldg(&trans[i * 32 + j]);
        float sc = __ldg(&st[j]) + e0;
        for (int t = 1; t < L; t++) {
            float e_cur = em_s[t * 32 + j];
            float bm = -1e30f;
            int bi = 0;
#pragma unroll
            for (int i = 0; i < 32; i++) {
                float v = __shfl_sync(0xffffffffu, sc, i) + trj[i];
                bi = (v > bm) ? i : bi;
                bm = fmaxf(bm, v);
            }
            d_hist[((size_t)b * 511 + (t - 1)) * KK + j] = (unsigned char)bi;
            sc = bm + e_cur;
        }
        float bm = sc + __ldg(&en[j]);
        int bi = j;
#pragma unroll
        for (int o = 16; o; o >>= 1) {
            float om = __shfl_xor_sync(0xffffffffu, bm, o);
            int oi = __shfl_xor_sync(0xffffffffu, bi, o);
            if (om > bm || (om == bm && oi < bi)) { bm = om; bi = oi; }
        }
        if (j == 0) d_last[b] = bi;
    }
}

// ============ K5: backtrack + loss =====================
__global__ void __launch_bounds__(128) k_back(
    const int* __restrict__ lengths, float* __restrict__ out, int out_size)
{
    const int b = blockIdx.x;
    const int tid = threadIdx.x;
    const bool has_loss = (out_size >= BB * TT + 1);
    const int off = has_loss ? 1 : 0;
    if (out_size < BB * TT) {
        if (b == 0 && tid == 0 && out_size >= 1) {
            float acc = 0.f;
            for (int q = 0; q < BB; q++) acc += d_nll[q];
            out[0] = -acc / (float)BB;
        }
        return;
    }
    __shared__ __align__(16) unsigned char hist_s[511 * KK];
    __shared__ int path[TT];
    {
        const int4* src = reinterpret_cast<const int4*>(&d_hist[(size_t)b * 511 * KK]);
        int4* dst = reinterpret_cast<int4*>(hist_s);
        for (int i = tid; i < (511 * KK) / 16; i += 128) dst[i] = src[i];
    }
    __syncthreads();
    const int L = lengths[b];
    if (tid == 0) {
        int tag = d_last[b];
        path[TT - 1] = tag;
        for (int s = TT - 2; s >= 0; s--) {
            int t = s + 1;
            int prev = (t < L) ? (int)hist_s[s * KK + tag] : tag;
            path[s] = prev;
            tag = prev;
        }
    }
    __syncthreads();
    for (int s = tid; s < TT; s += 128)
        out[off + b * TT + s] = (s < L) ? (float)path[s] : 0.f;
    if (b == 0 && tid == 0 && has_loss) {
        float acc = 0.f;
        for (int q = 0; q < BB; q++) acc += d_nll[q];
        out[0] = -acc / (float)BB;
    }
}

// ---------------- launch ----------------
extern "C" void kernel_launch(void* const* d_in, const int* in_sizes, int n_in,
                              void* d_out, int out_size)
{
    const float* x      = (const float*)d_in[0];
    const int* lengths  = (const int*)d_in[1];
    const int* targets  = (const int*)d_in[3];
    const float* Wihf   = (const float*)d_in[4];
    const float* Whhf   = (const float*)d_in[5];
    const float* bf_    = (const float*)d_in[6];
    const float* Wihb   = (const float*)d_in[7];
    const float* Whhb   = (const float*)d_in[8];
    const float* bb_    = (const float*)d_in[9];
    const float* Wclf   = (const float*)d_in[10];
    const float* bclf   = (const float*)d_in[11];
    const float* st     = (const float*)d_in[12];
    const float* en     = (const float*)d_in[13];
    const float* tr     = (const float*)d_in[14];

    static int attr_set = 0;
    if (!attr_set) {
        cudaFuncSetAttribute(k_crf, cudaFuncAttributeMaxDynamicSharedMemorySize, TT * KK * 4);
        attr_set = 1;
    }

    k_dummy<<<1, 32>>>();
    k_split<<<6528, 256>>>(x, lengths, Wihf, Wihb);
    k_gemm<<<dim3(256, 16, 2), 256>>>();
    k_lstm<<<128, 256>>>(Whhf, Whhb, bf_, bb_);
    k_emis<<<dim3(32, 8), 256>>>(lengths, Wclf, bclf);
    k_crf<<<32, 64, TT * KK * 4>>>(lengths, targets, st, en, tr);
    k_back<<<32, 128>>>(lengths, (float*)d_out, out_size);
}